// round 11
// baseline (speedup 1.0000x reference)
#include <cuda_runtime.h>
#include <math.h>

#define DIMX 128
#define DIMY 128
#define DIMZ 64
#define SY   128
#define SZ   16384
#define VOL  1048576           // DIMZ*DIMY*DIMX
#define NTOT 2097152           // 2 * VOL
#define TPB  256
#define NBLK (NTOT / TPB)      // 8192
// vectorized (float4) views
#define SY4   32
#define SZ4   4096
#define N4    (NTOT / 4)       // 524288
#define NBLK4 (N4 / TPB)       // 2048  (== 1<<11)

// 17 fields of NTOT floats:
// 0 P | 1 Y | 2 Hd | 3 S1 | 4 S2 | 5 S3
// 6 EA0 | 7 EA1 | 8 EA2 | 9 EB0 | 10 EB1 | 11 EB2 | 12 T0 | 13 T1 | 14 T2
// 15 D1 | 16 D2
__device__ __align__(16) float g_buf[17u * (size_t)NTOT];
__device__ double   g_acc[16];
// 0 sum_p | 1 sum_y | 2 sum_p*y | 3 ce | 4 conn | 5 dir
// 6 sumS1 | 7 sumS1*y | 8 sumS2 | 9 sumS2*p
// 10 inter1 | 11 union1 | 12 inter2 | 13 union2
__device__ unsigned g_mm[8];
// 0,1 rmax_t(b) | 2,3 rmin_t(b) | 4,5 rmax_p(b) | 6,7 rmin_p(b)

// ---------------------------------------------------------------- small helpers
__device__ __forceinline__ float4 min4(float4 a, float4 b) {
    return make_float4(fminf(a.x, b.x), fminf(a.y, b.y), fminf(a.z, b.z), fminf(a.w, b.w));
}
__device__ __forceinline__ float4 max4(float4 a, float4 b) {
    return make_float4(fmaxf(a.x, b.x), fmaxf(a.y, b.y), fmaxf(a.z, b.z), fmaxf(a.w, b.w));
}
__device__ __forceinline__ float hmax4(float4 a) {
    return fmaxf(fmaxf(a.x, a.y), fmaxf(a.z, a.w));
}
__device__ __forceinline__ float hmin4(float4 a) {
    return fminf(fminf(a.x, a.y), fminf(a.z, a.w));
}

// ---------------------------------------------------------------- reductions
__device__ __forceinline__ void block_add(double v, double* dst) {
    __shared__ double s_red[8];
#pragma unroll
    for (int o = 16; o > 0; o >>= 1) v += __shfl_down_sync(0xffffffffu, v, o);
    int lane = threadIdx.x & 31, wrp = threadIdx.x >> 5;
    if (lane == 0) s_red[wrp] = v;
    __syncthreads();
    if (threadIdx.x == 0) {
        double s = s_red[0];
#pragma unroll
        for (int k = 1; k < 8; ++k) s += s_red[k];
        atomicAdd(dst, s);
    }
    __syncthreads();
}

__device__ __forceinline__ void block_max_to(float v, unsigned* dst) {
    __shared__ float s_mx[8];
#pragma unroll
    for (int o = 16; o > 0; o >>= 1) v = fmaxf(v, __shfl_down_sync(0xffffffffu, v, o));
    int lane = threadIdx.x & 31, wrp = threadIdx.x >> 5;
    if (lane == 0) s_mx[wrp] = v;
    __syncthreads();
    if (threadIdx.x == 0) {
        float m = s_mx[0];
#pragma unroll
        for (int k = 1; k < 8; ++k) m = fmaxf(m, s_mx[k]);
        atomicMax(dst, __float_as_uint(m));
    }
    __syncthreads();
}

__device__ __forceinline__ void block_min_to(float v, unsigned* dst) {
    __shared__ float s_mn[8];
#pragma unroll
    for (int o = 16; o > 0; o >>= 1) v = fminf(v, __shfl_down_sync(0xffffffffu, v, o));
    int lane = threadIdx.x & 31, wrp = threadIdx.x >> 5;
    if (lane == 0) s_mn[wrp] = v;
    __syncthreads();
    if (threadIdx.x == 0) {
        float m = s_mn[0];
#pragma unroll
        for (int k = 1; k < 8; ++k) m = fminf(m, s_mn[k]);
        atomicMin(dst, __float_as_uint(m));
    }
    __syncthreads();
}

// ---------------------------------------------------------------- init
__global__ void k_init() {
    int t = threadIdx.x;
    if (t < 16) g_acc[t] = 0.0;
    if (t < 8)  g_mm[t] = (t == 2 || t == 3 || t == 6 || t == 7) ? 0x7F800000u : 0u;
}

// ---------------------------------------------------------------- fused prep + directional
// prep: prob/y/hard fields + dice/ce/conn sums.
// dir (Sobel, zero-pad cross-correlation), target side computed from tgt directly:
//   kx(d,h,w) = hsm[h]*wd[w]   (z summed, weight 1)
//   ky(d,h,w) = dsm[d]*wd[w]   (y summed, weight 1)   [transpose (0,1,3,2,4)]
//   kz(d,h,w) = wsm[w]*zd[d]   (y summed, weight 1)   [transpose (0,1,4,2,3)]
__global__ void __launch_bounds__(TPB) k_prep_dir(const float* __restrict__ net,
                                                  const int* __restrict__ tgt,
                                                  float* __restrict__ P,
                                                  float* __restrict__ Y,
                                                  float* __restrict__ Hd) {
    int i = blockIdx.x * TPB + threadIdx.x;
    int x = i & 127, y = (i >> 7) & 127, z = (i >> 14) & 63, b = i >> 20;
    int rem = i & (VOL - 1);
    const float* nb = net + (size_t)b * (2 * VOL);

    // ---- prep part (center voxel) ----
    float c0 = nb[rem];
    float c1 = nb[rem + VOL];
    int   t  = tgt[i];
    float yv = (t > 0) ? 1.f : 0.f;

    float m  = fmaxf(c0, c1);
    float e0 = expf(c0 - m), e1 = expf(c1 - m);
    float s  = e0 + e1;
    float p  = e1 / s;
    float lse = m + logf(s);
    float nll = lse - ((t != 0) ? c1 : c0);
    float hv  = (p > 0.5f) ? 1.f : 0.f;
    float cn  = fabsf(((c0 > 0.5f) ? 1.f : 0.f) - yv) +
                fabsf(((c1 > 0.5f) ? 1.f : 0.f) - yv);

    P[i] = p; Y[i] = yv; Hd[i] = hv;

    // ---- directional part (27-neighborhood of channel 0 + tgt) ----
    float gpx = 0.f, gpy = 0.f, gpz = 0.f, gtx = 0.f, gty = 0.f, gtz = 0.f;
#pragma unroll
    for (int dz = -1; dz <= 1; ++dz) {
        if ((unsigned)(z + dz) >= DIMZ) continue;
        float sa = (dz == 0) ? 2.f : 1.f;    // z-smooth
        float fdz = (float)dz;               // z-derivative
#pragma unroll
        for (int dy = -1; dy <= 1; ++dy) {
            if ((unsigned)(y + dy) >= DIMY) continue;
            float sh = (dy == 0) ? 2.f : 1.f;  // y-smooth
#pragma unroll
            for (int dx = -1; dx <= 1; ++dx) {
                if ((unsigned)(x + dx) >= DIMX) continue;
                int off = dz * SZ + dy * SY + dx;
                float vp = nb[rem + off];
                float vt = (tgt[i + off] > 0) ? 1.f : 0.f;
                float fdx = (float)dx;             // x-derivative
                float sw  = (dx == 0) ? 2.f : 1.f; // x-smooth
                gpx += vp * sh * fdx;    // kx: y-smooth * x-deriv
                gpy += vp * sa * fdx;    // ky: z-smooth * x-deriv
                gpz += vp * sw * fdz;    // kz: x-smooth * z-deriv
                gtx += vt * sh * fdx;
                gty += vt * sa * fdx;
                gtz += vt * sw * fdz;
            }
        }
    }
    float dot  = gpx * gtx + gpy * gty + gpz * gtz;
    float np   = sqrtf(gpx * gpx + gpy * gpy + gpz * gpz);
    float nt   = sqrtf(gtx * gtx + gty * gty + gtz * gtz);
    float invp = 1.f / fmaxf(np, 1e-12f);
    float invt = 1.f / fmaxf(nt, 1e-12f);
    float den  = fmaxf((np * invp) * (nt * invt), 1e-8f);
    float ratio = (dot * invp * invt) / den;

    // ---- reductions ----
    block_add((double)p,        &g_acc[0]);
    block_add((double)yv,       &g_acc[1]);
    block_add((double)(p * yv), &g_acc[2]);
    block_add((double)nll,      &g_acc[3]);
    block_add((double)cn,       &g_acc[4]);
    block_add((double)ratio,    &g_acc[5]);
}

// ---------------------------------------------------------------- morphology (vectorized float4 along x)
// scalar 7-point erode (used for float4-boundary positions)
__device__ __forceinline__ float erode_at(const float* __restrict__ in,
                                          int i, int x, int y, int z) {
    float v = in[i];
    if (x > 0)        v = fminf(v, in[i - 1]);
    if (x < DIMX - 1) v = fminf(v, in[i + 1]);
    if (y > 0)        v = fminf(v, in[i - SY]);
    if (y < DIMY - 1) v = fminf(v, in[i + SY]);
    if (z > 0)        v = fminf(v, in[i - SZ]);
    if (z < DIMZ - 1) v = fminf(v, in[i + SZ]);
    return v;
}

// vector 7-point erode at float4 index i4 (x4 = i4 & 31)
__device__ __forceinline__ float4 erode4(const float* __restrict__ in,
                                         int i4, int x4, int y, int z) {
    const float4* in4 = (const float4*)in;
    float4 c = in4[i4];
    float4 v;
    v.x = fminf(c.x, c.y);
    v.y = fminf(c.x, fminf(c.y, c.z));
    v.z = fminf(c.y, fminf(c.z, c.w));
    v.w = fminf(c.z, c.w);
    if (x4 > 0)        v.x = fminf(v.x, in[i4 * 4 - 1]);
    if (x4 < SY4 - 1)  v.w = fminf(v.w, in[i4 * 4 + 4]);
    if (y > 0)         v = min4(v, in4[i4 - SY4]);
    if (y < DIMY - 1)  v = min4(v, in4[i4 + SY4]);
    if (z > 0)         v = min4(v, in4[i4 - SZ4]);
    if (z < DIMZ - 1)  v = min4(v, in4[i4 + SZ4]);
    return v;
}

// FUSED over 3 independent images: E_r = erode(in_r); t_r = maxX(E_r)
// grid = 3*NBLK4; r = blockIdx.x >> 11 selects the image.
// store_E == 0 on the final iteration (E is dead afterwards).
__global__ void __launch_bounds__(TPB) k_skel_a3(const float* __restrict__ in0,
                                                 const float* __restrict__ in1,
                                                 const float* __restrict__ in2,
                                                 float* __restrict__ t0,
                                                 float* __restrict__ t1,
                                                 float* __restrict__ t2,
                                                 float* __restrict__ E0,
                                                 float* __restrict__ E1,
                                                 float* __restrict__ E2,
                                                 int store_E) {
    int r = blockIdx.x >> 11;
    const float* in = (r == 0) ? in0 : (r == 1) ? in1 : in2;
    float* t = (r == 0) ? t0 : (r == 1) ? t1 : t2;
    float* E = (r == 0) ? E0 : (r == 1) ? E1 : E2;

    int i4 = (blockIdx.x & (NBLK4 - 1)) * TPB + threadIdx.x;
    int x4 = i4 & 31, y = (i4 >> 5) & 127, z = (i4 >> 12) & 63;
    float4 e = erode4(in, i4, x4, y, z);
    if (store_E) ((float4*)E)[i4] = e;
    float4 o;
    o.x = fmaxf(e.x, e.y);
    o.y = fmaxf(e.x, fmaxf(e.y, e.z));
    o.z = fmaxf(e.y, fmaxf(e.z, e.w));
    o.w = fmaxf(e.z, e.w);
    if (x4 > 0)       o.x = fmaxf(o.x, erode_at(in, i4 * 4 - 1, x4 * 4 - 1, y, z));
    if (x4 < SY4 - 1) o.w = fmaxf(o.w, erode_at(in, i4 * 4 + 4, x4 * 4 + 4, y, z));
    ((float4*)t)[i4] = o;
}

// FUSED over 3 images: open = maxYZ(t); delta = relu(img - open); skel update.
__global__ void __launch_bounds__(TPB) k_skel_b3(const float* __restrict__ t0,
                                                 const float* __restrict__ t1,
                                                 const float* __restrict__ t2,
                                                 const float* __restrict__ img0,
                                                 const float* __restrict__ img1,
                                                 const float* __restrict__ img2,
                                                 float* __restrict__ sk0,
                                                 float* __restrict__ sk1,
                                                 float* __restrict__ sk2,
                                                 int first) {
    int r = blockIdx.x >> 11;
    const float* t   = (r == 0) ? t0 : (r == 1) ? t1 : t2;
    const float* img = (r == 0) ? img0 : (r == 1) ? img1 : img2;
    float* skel      = (r == 0) ? sk0 : (r == 1) ? sk1 : sk2;

    int i4 = (blockIdx.x & (NBLK4 - 1)) * TPB + threadIdx.x;
    int y = (i4 >> 5) & 127, z = (i4 >> 12) & 63;
    const float4* t4 = (const float4*)t;
    float4 o = make_float4(-INFINITY, -INFINITY, -INFINITY, -INFINITY);
#pragma unroll
    for (int dz = -1; dz <= 1; ++dz) {
        if ((unsigned)(z + dz) >= DIMZ) continue;
#pragma unroll
        for (int dy = -1; dy <= 1; ++dy) {
            if ((unsigned)(y + dy) >= DIMY) continue;
            o = max4(o, t4[i4 + dz * SZ4 + dy * SY4]);
        }
    }
    float4 e = ((const float4*)img)[i4];
    float4 s = first ? make_float4(0.f, 0.f, 0.f, 0.f) : ((const float4*)skel)[i4];
    float4 rr;
    float dx0 = fmaxf(e.x - o.x, 0.f); rr.x = s.x + fmaxf(dx0 - s.x * dx0, 0.f);
    float dy0 = fmaxf(e.y - o.y, 0.f); rr.y = s.y + fmaxf(dy0 - s.y * dy0, 0.f);
    float dz0 = fmaxf(e.z - o.z, 0.f); rr.z = s.z + fmaxf(dz0 - s.z * dz0, 0.f);
    float dw0 = fmaxf(e.w - o.w, 0.f); rr.w = s.w + fmaxf(dw0 - s.w * dw0, 0.f);
    ((float4*)skel)[i4] = rr;
}

// FUSED over 2 masks: acc (+)= cur ; nxt = minpool3x3x3(cur)
__global__ void __launch_bounds__(TPB) k_edt_step2(const float* __restrict__ cur0,
                                                   const float* __restrict__ cur1,
                                                   float* __restrict__ acc0,
                                                   float* __restrict__ acc1,
                                                   float* __restrict__ nxt0,
                                                   float* __restrict__ nxt1,
                                                   int first) {
    int r = blockIdx.x >> 11;
    const float* cur = (r == 0) ? cur0 : cur1;
    float* acc = (r == 0) ? acc0 : acc1;
    float* nxt = (r == 0) ? nxt0 : nxt1;

    int i4 = (blockIdx.x & (NBLK4 - 1)) * TPB + threadIdx.x;
    int x4 = i4 & 31, y = (i4 >> 5) & 127, z = (i4 >> 12) & 63;
    const float4* cur4 = (const float4*)cur;
    float4 c = cur4[i4];
    float4* acc4 = (float4*)acc;
    if (first) {
        acc4[i4] = c;
    } else {
        float4 a = acc4[i4];
        acc4[i4] = make_float4(a.x + c.x, a.y + c.y, a.z + c.z, a.w + c.w);
    }
    float4 v = make_float4(INFINITY, INFINITY, INFINITY, INFINITY);
#pragma unroll
    for (int dz = -1; dz <= 1; ++dz) {
        if ((unsigned)(z + dz) >= DIMZ) continue;
#pragma unroll
        for (int dy = -1; dy <= 1; ++dy) {
            if ((unsigned)(y + dy) >= DIMY) continue;
            int b4 = i4 + dz * SZ4 + dy * SY4;
            float4 rr = cur4[b4];
            float4 m;
            m.x = fminf(rr.x, rr.y);
            m.y = fminf(rr.x, fminf(rr.y, rr.z));
            m.z = fminf(rr.y, fminf(rr.z, rr.w));
            m.w = fminf(rr.z, rr.w);
            if (x4 > 0)       m.x = fminf(m.x, cur[b4 * 4 - 1]);
            if (x4 < SY4 - 1) m.w = fminf(m.w, cur[b4 * 4 + 4]);
            v = min4(v, m);
        }
    }
    ((float4*)nxt)[i4] = v;
}

// ---------------------------------------------------------------- radius reductions + clDice sums (float4)
// D1/D2 hold 15 of the 16 EDT terms; C1/C2 hold the 16th (last minpool output).
// dist = D + C, folded here instead of a separate elementwise pass.
// grid = NBLK4; per-batch float4 count = 2^18, so b = i4 >> 18 is block-uniform.
__global__ void __launch_bounds__(TPB) k_radius(const float* __restrict__ P,
                                                const float* __restrict__ Y,
                                                const float* __restrict__ Hd,
                                                const float* __restrict__ S1,
                                                const float* __restrict__ S2,
                                                const float* __restrict__ S3,
                                                const float* __restrict__ D1,
                                                const float* __restrict__ D2,
                                                const float* __restrict__ C1,
                                                const float* __restrict__ C2) {
    int i4 = blockIdx.x * TPB + threadIdx.x;
    int b = i4 >> 18;                     // constant within a block
    float4 yv = ((const float4*)Y)[i4];
    float4 p  = ((const float4*)P)[i4];
    float4 h  = ((const float4*)Hd)[i4];
    float4 s1 = ((const float4*)S1)[i4];
    float4 s2 = ((const float4*)S2)[i4];
    float4 s3 = ((const float4*)S3)[i4];
    float4 d1 = ((const float4*)D1)[i4];
    float4 d2 = ((const float4*)D2)[i4];
    float4 c1 = ((const float4*)C1)[i4];
    float4 c2 = ((const float4*)C2)[i4];

    float4 sr_t, sr_p;
    {
        float v, s3p, sb;
        v = (d1.x + c1.x) * yv.x * s2.x; sr_t.x = v;
        v = (d1.y + c1.y) * yv.y * s2.y; sr_t.y = v;
        v = (d1.z + c1.z) * yv.z * s2.z; sr_t.z = v;
        v = (d1.w + c1.w) * yv.w * s2.w; sr_t.w = v;
        s3p = s3.x * p.x; sb = (s3p > 0.5f) ? 1.f : 0.f; sr_p.x = (d2.x + c2.x) * h.x * sb;
        s3p = s3.y * p.y; sb = (s3p > 0.5f) ? 1.f : 0.f; sr_p.y = (d2.y + c2.y) * h.y * sb;
        s3p = s3.z * p.z; sb = (s3p > 0.5f) ? 1.f : 0.f; sr_p.z = (d2.z + c2.z) * h.z * sb;
        s3p = s3.w * p.w; sb = (s3p > 0.5f) ? 1.f : 0.f; sr_p.w = (d2.w + c2.w) * h.w * sb;
    }

    block_max_to(hmax4(sr_t), &g_mm[0 + b]);
    block_min_to(hmin4(sr_t), &g_mm[2 + b]);
    block_max_to(hmax4(sr_p), &g_mm[4 + b]);
    block_min_to(hmin4(sr_p), &g_mm[6 + b]);

    double sum_s1  = (double)s1.x + s1.y + s1.z + s1.w;
    double sum_s1y = (double)(s1.x * yv.x) + (s1.y * yv.y) + (s1.z * yv.z) + (s1.w * yv.w);
    double sum_s2  = (double)s2.x + s2.y + s2.z + s2.w;
    double sum_s2p = (double)(s2.x * p.x) + (s2.y * p.y) + (s2.z * p.z) + (s2.w * p.w);
    block_add(sum_s1,  &g_acc[6]);
    block_add(sum_s1y, &g_acc[7]);
    block_add(sum_s2,  &g_acc[8]);
    block_add(sum_s2p, &g_acc[9]);
}

// ---------------------------------------------------------------- union-loss sums (float4)
__global__ void __launch_bounds__(TPB) k_unionloss(const float* __restrict__ P,
                                                   const float* __restrict__ Y,
                                                   const float* __restrict__ Hd,
                                                   const float* __restrict__ S2,
                                                   const float* __restrict__ S3,
                                                   const float* __restrict__ D1,
                                                   const float* __restrict__ D2,
                                                   const float* __restrict__ C1,
                                                   const float* __restrict__ C2) {
    int i4 = blockIdx.x * TPB + threadIdx.x;
    int b = i4 >> 18;
    float rmax_t = fmaxf(__uint_as_float(g_mm[0 + b]), 1.f);
    float rmin_t = fmaxf(__uint_as_float(g_mm[2 + b]), 1.f);
    float rmax_p = fmaxf(__uint_as_float(g_mm[4 + b]), 1.f);
    float rmin_p = fmaxf(__uint_as_float(g_mm[6 + b]), 1.f);

    float4 yv = ((const float4*)Y)[i4];
    float4 p  = ((const float4*)P)[i4];
    float4 h  = ((const float4*)Hd)[i4];
    float4 s2 = ((const float4*)S2)[i4];
    float4 s3 = ((const float4*)S3)[i4];
    float4 d1 = ((const float4*)D1)[i4];
    float4 d2 = ((const float4*)D2)[i4];
    float4 c1 = ((const float4*)C1)[i4];
    float4 c2 = ((const float4*)C2)[i4];

    double inter1 = 0.0, uni1 = 0.0, inter2 = 0.0, uni2 = 0.0;
    const float* yvp = &yv.x;  const float* pp  = &p.x;
    const float* hp  = &h.x;   const float* s2p_ = &s2.x;
    const float* s3p_ = &s3.x; const float* d1p = &d1.x;
    const float* d2p = &d2.x;  const float* c1p = &c1.x;
    const float* c2p = &c2.x;
#pragma unroll
    for (int k = 0; k < 4; ++k) {
        float yvk = yvp[k], pk = pp[k], hk = hp[k], s2k = s2p_[k];
        float s3pk = s3p_[k] * pk;

        // target-side weights (prob_flag = False)
        float dist_t = (d1p[k] + c1p[k]) * yvk;
        float sr_t   = dist_t * s2k;
        float q_vl   = fminf(dist_t, rmax_t) / rmax_t * yvk;
        float It     = (rmax_t - sr_t + rmin_t) / rmax_t;
        float q_sl   = It * It * s2k * s2k;

        // pred-side weights (prob_flag = True)
        float sb     = (s3pk > 0.5f) ? 1.f : 0.f;
        float dist_p = (d2p[k] + c2p[k]) * hk;
        float sr_p   = dist_p * sb;
        float q_vp   = fminf(dist_p, rmax_p) / rmax_p * pk;
        float Ip     = (rmax_p - sr_p + rmin_p) / rmax_p;
        float q_sp   = Ip * Ip * sb * s3pk;

        inter1 += (double)(q_sp * powf(q_sp + 1e-4f, 0.7f) * q_vl);
        uni1   += (double)(q_sp * (0.1f * q_sp + 0.9f * q_vl));
        inter2 += (double)(q_sl * powf(q_vp + 1e-4f, 0.7f) * q_sl);
        uni2   += (double)(q_sl * (0.1f * q_vp + 0.9f * q_sl));
    }

    block_add(inter1, &g_acc[10]);
    block_add(uni1,   &g_acc[11]);
    block_add(inter2, &g_acc[12]);
    block_add(uni2,   &g_acc[13]);
}

// ---------------------------------------------------------------- final combine
__global__ void k_final(float* __restrict__ out) {
    double Nd = (double)NTOT;
    double sum_p = g_acc[0], sum_y = g_acc[1], tp = g_acc[2];
    double dice = -((2.0 * tp + 1e-5) / (sum_p + sum_y + 1e-5));
    double ce   = g_acc[3] / Nd;
    double conn = g_acc[4] / (2.0 * Nd);
    double dirl = 1.0 - g_acc[5] / Nd;
    double tprec = (g_acc[7] + 1.0) / (g_acc[6] + 1.0);
    double tsens = (g_acc[9] + 1.0) / (g_acc[8] + 1.0);
    double cl = 1.0 - 2.0 * tprec * tsens / (tprec + tsens);
    double u1 = 1.0 - (g_acc[10] + 1.0) / (g_acc[11] + 1.0);
    double u2 = 1.0 - (g_acc[12] + 1.0) / (g_acc[13] + 1.0);
    out[0] = (float)(dice + ce + cl + dirl + conn + u1 + u2);
}

// ---------------------------------------------------------------- host orchestration
extern "C" void kernel_launch(void* const* d_in, const int* in_sizes, int n_in,
                              void* d_out, int out_size) {
    const float* net = (const float*)d_in[0];
    const int*   tgt = (const int*)d_in[1];

    void* bp = nullptr;
    cudaGetSymbolAddress(&bp, g_buf);
    float* B   = (float*)bp;
    float* P   = B + 0ull  * NTOT;
    float* Y   = B + 1ull  * NTOT;
    float* Hd  = B + 2ull  * NTOT;
    float* S1  = B + 3ull  * NTOT;
    float* S2  = B + 4ull  * NTOT;
    float* S3  = B + 5ull  * NTOT;
    float* EA0 = B + 6ull  * NTOT;
    float* EA1 = B + 7ull  * NTOT;
    float* EA2 = B + 8ull  * NTOT;
    float* EB0 = B + 9ull  * NTOT;
    float* EB1 = B + 10ull * NTOT;
    float* EB2 = B + 11ull * NTOT;
    float* T0  = B + 12ull * NTOT;
    float* T1  = B + 13ull * NTOT;
    float* T2  = B + 14ull * NTOT;
    float* D1  = B + 15ull * NTOT;
    float* D2  = B + 16ull * NTOT;

    k_init<<<1, 32>>>();
    k_prep_dir<<<NBLK, TPB>>>(net, tgt, P, Y, Hd);

    // --- three soft_skel chains fused per step (P->S1, Y->S2, Hd->S3) ---
    {
        const float* img[3] = {P, Y, Hd};
        float* pa[3] = {EA0, EA1, EA2};
        float* pb[3] = {EB0, EB1, EB2};
        for (int it = 0; it < 11; ++it) {   // it 0 = skel init, then 10 loop iters
            float** E = (it & 1) ? pb : pa;
            int store_E = (it < 10) ? 1 : 0;   // E dead after last iteration
            k_skel_a3<<<3 * NBLK4, TPB>>>(img[0], img[1], img[2],
                                          T0, T1, T2,
                                          E[0], E[1], E[2], store_E);
            k_skel_b3<<<3 * NBLK4, TPB>>>(T0, T1, T2,
                                          img[0], img[1], img[2],
                                          S1, S2, S3, (it == 0) ? 1 : 0);
            img[0] = E[0]; img[1] = E[1]; img[2] = E[2];  // img_{t+1} = erode(img_t)
        }
    }

    // --- two EDT chains fused per step (Y->D1, Hd->D2) ---
    // Run 15 accumulate+pool steps; the 16th term (last pool output, in cur[])
    // is folded into k_radius / k_unionloss as dist = D + C.
    const float* curl[2] = {Y, Hd};
    {
        float* pa[2] = {EA0, EA1};
        float* pb[2] = {EB0, EB1};
        for (int it = 0; it < 15; ++it) {
            float** nxt = (it & 1) ? pb : pa;
            k_edt_step2<<<2 * NBLK4, TPB>>>(curl[0], curl[1], D1, D2,
                                            nxt[0], nxt[1], (it == 0) ? 1 : 0);
            curl[0] = nxt[0]; curl[1] = nxt[1];
        }
        // after it=14, curl[] holds minpool^15 — the 16th accumulation term
    }

    k_radius<<<NBLK4, TPB>>>(P, Y, Hd, S1, S2, S3, D1, D2, curl[0], curl[1]);
    k_unionloss<<<NBLK4, TPB>>>(P, Y, Hd, S2, S3, D1, D2, curl[0], curl[1]);
    k_final<<<1, 1>>>((float*)d_out);
}